// round 11
// baseline (speedup 1.0000x reference)
#include <cuda_runtime.h>
#include <math.h>
#include <stdint.h>

// Problem constants
#define Bb  4
#define Aa  3
#define Ss  1024
#define Hh  768
#define NHh 12
#define HDd 64

// Device scratch (allocation-free rule: __device__ globals)
__device__ float g_Q  [Bb*Ss*Hh];          // Q projection (tf32 vals, pre-scaled 1/8)
__device__ float g_K  [Bb*Aa*Ss*Hh];       // K projection (tf32 vals)
__device__ float g_V  [Bb*Aa*Ss*Hh];       // V projection (tf32 vals)
__device__ float g_att[Bb*Ss*Hh];          // attended (tf32 vals)
__device__ float g_O  [Bb*Ss*Hh];          // pre-LN (fp32)
// tf32-rounded copies of GEMM inputs (conversion-free cp.async loads)
__device__ float g_Xq [Bb*Ss*Hh];
__device__ float g_Xkv[Bb*Aa*Ss*Hh];
__device__ float g_Wqc[Hh*Hh];
__device__ float g_Wkc[Hh*Hh];
__device__ float g_Wvc[Hh*Hh];
__device__ float g_Woc[Hh*Hh];

// ===========================================================================
// helpers (arch-portable: compiles for compute_103 without 'a')
// ===========================================================================
__device__ __forceinline__ uint32_t f2tf32(float x) {
    uint32_t r;
    asm("cvt.rna.tf32.f32 %0, %1;" : "=r"(r) : "f"(x));
    return r;
}

__device__ __forceinline__ uint32_t smem_u32(const void* p) {
    uint32_t a;
    asm("{ .reg .u64 t; cvta.to.shared.u64 t, %1; cvt.u32.u64 %0, t; }"
        : "=r"(a) : "l"(p));
    return a;
}

__device__ __forceinline__ void cp_async16(uint32_t dst, const void* src) {
    asm volatile("cp.async.ca.shared.global [%0], [%1], 16;"
                 :: "r"(dst), "l"(src) : "memory");
}
__device__ __forceinline__ void cp_commit() {
    asm volatile("cp.async.commit_group;" ::: "memory");
}
template<int N>
__device__ __forceinline__ void cp_wait() {
    asm volatile("cp.async.wait_group %0;" :: "n"(N) : "memory");
}

// D(16x8,f32) += A(16x8,tf32) * B(8x8,tf32)
__device__ __forceinline__ void mma_tf32(float c[4], const uint32_t a[4],
                                         const uint32_t b[2]) {
    asm volatile(
        "mma.sync.aligned.m16n8k8.row.col.f32.tf32.tf32.f32 "
        "{%0,%1,%2,%3}, {%4,%5,%6,%7}, {%8,%9}, {%0,%1,%2,%3};"
        : "+f"(c[0]), "+f"(c[1]), "+f"(c[2]), "+f"(c[3])
        : "r"(a[0]), "r"(a[1]), "r"(a[2]), "r"(a[3]), "r"(b[0]), "r"(b[1]));
}

// Elementwise tf32 rounding pass (producer-side rounding for cp.async GEMMs)
__global__ __launch_bounds__(256)
void cvt_tf32_kernel(const float* __restrict__ in, float* __restrict__ out, int n4)
{
    int i = blockIdx.x * blockDim.x + threadIdx.x;
    if (i < n4) {
        float4 v = ((const float4*)in)[i];
        uint4 o;
        o.x = f2tf32(v.x); o.y = f2tf32(v.y);
        o.z = f2tf32(v.z); o.w = f2tf32(v.w);
        ((uint4*)out)[i] = o;
    }
}

// ===========================================================================
// GEMM via mma.sync tf32 + cp.async (inputs pre-rounded to tf32 in gmem).
// BM=BN=128, BK=32, 256 threads = 8 warps (4 M x 2 N, warp tile 32x64).
// 2-stage cp.async, ONE __syncthreads per chunk: the sync proves both that
// chunk kc is visible and that all warps consumed chunk kc-1, so the issue
// of chunk kc+1 (into kc-1's buffer) placed after the sync is safe and
// overlaps compute(kc).
// Smem pitch 36 floats (144B, 16B-aligned rows; conflict-free fragments).
// smem = 2 stages * 2 arrays * 128*36*4 = 73,728 B -> 2 blocks/SM.
// ===========================================================================
#define GP 36
#define GEMM_STAGE_DW (2 * 128 * GP)              // A+B dwords per stage
#define GEMM_SMEM (2 * GEMM_STAGE_DW * 4)         // 73,728 B

template<bool ADD, bool TFOUT>
__global__ __launch_bounds__(256, 2)
void gemm_cp(const float* __restrict__ X, const float* __restrict__ W,
             const float* __restrict__ bias, const float* __restrict__ res,
             float* __restrict__ out, int M, int N, int K, float oscale)
{
    extern __shared__ float sm[];
    const uint32_t smBase = smem_u32(sm);

    const int tid  = threadIdx.x;
    const int lane = tid & 31;
    const int gid  = lane >> 2;
    const int tig  = lane & 3;
    const int wid  = tid >> 5;
    const int wm   = (wid >> 1) * 32;
    const int wn   = (wid & 1) * 64;
    const int m0   = blockIdx.y * 128;
    const int n0   = blockIdx.x * 128;

    auto issue = [&](int buf, int k0) {
#pragma unroll
        for (int p = 0; p < 4; p++) {
            int idx = p * 256 + tid;
            int r = idx >> 3, c4 = (idx & 7) * 4;
            uint32_t off = (uint32_t)(buf * GEMM_STAGE_DW + r * GP + c4) * 4;
            cp_async16(smBase + off, X + (size_t)(m0 + r) * K + k0 + c4);
            cp_async16(smBase + off + 128 * GP * 4, W + (size_t)(n0 + r) * K + k0 + c4);
        }
        cp_commit();
    };

    float acc[2][8][4];
#pragma unroll
    for (int mi = 0; mi < 2; mi++)
#pragma unroll
        for (int ni = 0; ni < 8; ni++)
#pragma unroll
            for (int j = 0; j < 4; j++) acc[mi][ni][j] = 0.f;

    issue(0, 0);

    const int NK = K / 32;   // 24
    for (int kc = 0; kc < NK; kc++) {
        cp_wait<0>();        // chunk kc complete (issued previous iter)
        __syncthreads();     // visible to all; chunk kc-1 consumed by all
        if (kc + 1 < NK) issue((kc + 1) & 1, (kc + 1) * 32);

        const uint32_t* Au = (const uint32_t*)sm + (kc & 1) * GEMM_STAGE_DW;
        const uint32_t* Bu = Au + 128 * GP;
#pragma unroll
        for (int ks = 0; ks < 4; ks++) {
            const int kk = ks * 8;
            uint32_t a[2][4], b[8][2];
#pragma unroll
            for (int mi = 0; mi < 2; mi++) {
                int rb = wm + mi * 16;
                a[mi][0] = Au[(rb + gid)     * GP + kk + tig];
                a[mi][1] = Au[(rb + gid + 8) * GP + kk + tig];
                a[mi][2] = Au[(rb + gid)     * GP + kk + tig + 4];
                a[mi][3] = Au[(rb + gid + 8) * GP + kk + tig + 4];
            }
#pragma unroll
            for (int ni = 0; ni < 8; ni++) {
                int nb = wn + ni * 8 + gid;
                b[ni][0] = Bu[nb * GP + kk + tig];
                b[ni][1] = Bu[nb * GP + kk + tig + 4];
            }
#pragma unroll
            for (int mi = 0; mi < 2; mi++)
#pragma unroll
                for (int ni = 0; ni < 8; ni++)
                    mma_tf32(acc[mi][ni], a[mi], b[ni]);
        }
    }

    // Epilogue
#pragma unroll
    for (int mi = 0; mi < 2; mi++) {
        int r0 = m0 + wm + mi * 16 + gid;
        int r1 = r0 + 8;
#pragma unroll
        for (int ni = 0; ni < 8; ni++) {
            int col = n0 + wn + ni * 8 + 2 * tig;
            float b0 = bias[col], b1 = bias[col + 1];
            float2 v0 = make_float2(acc[mi][ni][0] + b0, acc[mi][ni][1] + b1);
            float2 v1 = make_float2(acc[mi][ni][2] + b0, acc[mi][ni][3] + b1);
            if (ADD) {
                float2 ra = *(const float2*)(res + (size_t)r0 * N + col);
                float2 rb = *(const float2*)(res + (size_t)r1 * N + col);
                v0.x += ra.x; v0.y += ra.y;
                v1.x += rb.x; v1.y += rb.y;
            }
            if (TFOUT) {
                v0.x = __uint_as_float(f2tf32(v0.x * oscale));
                v0.y = __uint_as_float(f2tf32(v0.y * oscale));
                v1.x = __uint_as_float(f2tf32(v1.x * oscale));
                v1.y = __uint_as_float(f2tf32(v1.y * oscale));
            }
            *(float2*)(out + (size_t)r0 * N + col) = v0;
            *(float2*)(out + (size_t)r1 * N + col) = v1;
        }
    }
}

// ===========================================================================
// Attention v6 — 3-stage cp.async, ONE __syncthreads per chunk.
//
// Block: 128 q x (b,h), 512 threads = 16 warps, 1 block/SM.
// Warp (wm=(wid>>1)*16 q-rows, ws=wid&1 key-half) owns keys
// [ws*16, ws*16+16) x 3 adapters (48 k-rows) and the full d=64 per chunk.
// P stays in registers via the sigma=[0,2,4,6,1,3,5,7] fragment identity.
//
// Pipeline (prefetch distance 2): prologue issues chunks 0,1. Iter ic:
// wait (chunk ic done: <1 pending while issuing, 0 at tail), sync (also
// proves all warps consumed chunk ic-1), issue chunk ic+2 into ic-1's
// buffer, compute chunk ic.
// smem = 6 buffers * 96*68*4 = 156,672 B.
// ===========================================================================
#define KP 68
#define CHUNK_DW (96 * KP)
#define ATTN_SMEM (6 * CHUNK_DW * 4)       // 156,672 B

__global__ __launch_bounds__(512, 1)
void attn6_kernel(const float* __restrict__ Q, const float* __restrict__ K,
                  const float* __restrict__ V, float* __restrict__ O)
{
    extern __shared__ float sm[];
    uint32_t* smU = (uint32_t*)sm;
    const uint32_t smBase = smem_u32(sm);

    const int q0  = blockIdx.x * 128;
    const int h   = blockIdx.y;
    const int b   = blockIdx.z;
    const int tid  = threadIdx.x;
    const int lane = tid & 31;
    const int gid  = lane >> 2;
    const int tig  = lane & 3;
    const int wid  = tid >> 5;
    const int wm   = (wid >> 1) * 16;   // q rows: 0..112
    const int ws   = wid & 1;           // key half

    const size_t kvHead = (size_t)h * HDd;

    auto issue_chunk = [&](int buf, int s0) {
#pragma unroll
        for (int p = 0; p < 3; p++) {
            int i = p * 512 + tid;
            int r = i >> 4, c4 = (i & 15) * 4;
            int a = r >> 5, s = r & 31;
            size_t gb = ((size_t)((b * Aa + a) * Ss + s0 + s)) * Hh + kvHead + c4;
            uint32_t so = (uint32_t)(r * KP + c4) * 4;
            cp_async16(smBase + buf * (CHUNK_DW * 4) + so, K + gb);
            cp_async16(smBase + (3 + buf) * (CHUNK_DW * 4) + so, V + gb);
        }
        cp_commit();
    };

    // Q fragments in registers (pre-scaled by 1/8, pre-rounded tf32)
    uint32_t qf[8][4];
    {
        const float* Qb = Q + (((size_t)((b * Ss + q0 + wm) * NHh + h)) << 6);
#pragma unroll
        for (int ks = 0; ks < 8; ks++) {
            int c = ks * 8 + tig;
            qf[ks][0] = __float_as_uint(Qb[(size_t)gid * 768 + c]);
            qf[ks][1] = __float_as_uint(Qb[(size_t)(gid + 8) * 768 + c]);
            qf[ks][2] = __float_as_uint(Qb[(size_t)gid * 768 + c + 4]);
            qf[ks][3] = __float_as_uint(Qb[(size_t)(gid + 8) * 768 + c + 4]);
        }
    }

    float co[8][4];
#pragma unroll
    for (int nd = 0; nd < 8; nd++)
#pragma unroll
        for (int j = 0; j < 4; j++) co[nd][j] = 0.f;

    issue_chunk(0, 0);
    issue_chunk(1, 32);

    for (int ic = 0; ic < 32; ic++) {
        if (ic < 30) cp_wait<1>();   // chunk ic done; ic+1 may be in flight
        else         cp_wait<0>();   // tail: nothing more issued
        __syncthreads();             // data visible; chunk ic-1 consumed
        if (ic + 2 < 32) {
            int buf = ic + 2;
            buf -= (buf >= 3) ? 3 : 0; buf -= (buf >= 3) ? 3 : 0;
            // (ic+2) % 3 without divide
            issue_chunk((ic + 2) % 3, (ic + 2) * 32);
        }

        int cb = ic % 3;
        const uint32_t* smK = smU + cb * CHUNK_DW;
        const uint32_t* smV = smU + (3 + cb) * CHUNK_DW;

        // ---- scores ----
        float cs[3][2][4];
#pragma unroll
        for (int ad = 0; ad < 3; ad++)
#pragma unroll
            for (int ni = 0; ni < 2; ni++)
#pragma unroll
                for (int j = 0; j < 4; j++) cs[ad][ni][j] = 0.f;

#pragma unroll
        for (int ks = 0; ks < 8; ks++) {
            const int kk = ks * 8;
#pragma unroll
            for (int ad = 0; ad < 3; ad++)
#pragma unroll
                for (int ni = 0; ni < 2; ni++) {
                    int krow = ad * 32 + ws * 16 + ni * 8 + gid;
                    uint32_t bb[2];
                    bb[0] = smK[krow * KP + kk + tig];
                    bb[1] = smK[krow * KP + kk + tig + 4];
                    mma_tf32(cs[ad][ni], qf[ks], bb);
                }
        }

        // ---- softmax over adapters (registers) ----
#pragma unroll
        for (int ni = 0; ni < 2; ni++)
#pragma unroll
            for (int pos = 0; pos < 4; pos++) {
                float z0 = cs[0][ni][pos];
                float z1 = cs[1][ni][pos];
                float z2 = cs[2][ni][pos];
                float m  = fmaxf(z0, fmaxf(z1, z2));
                float e0 = __expf(z0 - m);
                float e1 = __expf(z1 - m);
                float e2 = __expf(z2 - m);
                float inv = 1.f / (e0 + e1 + e2);
                cs[0][ni][pos] = __uint_as_float(f2tf32(e0 * inv));
                cs[1][ni][pos] = __uint_as_float(f2tf32(e1 * inv));
                cs[2][ni][pos] = __uint_as_float(f2tf32(e2 * inv));
            }

        // ---- PV (P from registers via sigma identity) ----
#pragma unroll
        for (int ad = 0; ad < 3; ad++)
#pragma unroll
            for (int ni = 0; ni < 2; ni++) {
                uint32_t A[4];
                A[0] = __float_as_uint(cs[ad][ni][0]);
                A[1] = __float_as_uint(cs[ad][ni][2]);
                A[2] = __float_as_uint(cs[ad][ni][1]);
                A[3] = __float_as_uint(cs[ad][ni][3]);
                const int base = ad * 32 + ws * 16 + ni * 8;
                const uint32_t* v0 = &smV[(base + 2 * tig)     * KP + gid];
                const uint32_t* v1 = &smV[(base + 2 * tig + 1) * KP + gid];
#pragma unroll
                for (int nd = 0; nd < 8; nd++) {
                    uint32_t bb[2] = { v0[nd * 8], v1[nd * 8] };
                    mma_tf32(co[nd], A, bb);
                }
            }
    }

    // ---- cross-half reduction and writeout (tf32-rounded for O-proj) ----
    __syncthreads();
    float* red = sm;
    const int wmg = wid >> 1;
    if (ws == 1) {
#pragma unroll
        for (int nd = 0; nd < 8; nd++) {
            int c = nd * 8 + 2 * tig;
            *(float2*)&red[(wmg * 16 + gid) * 66 + c] =
                make_float2(co[nd][0], co[nd][1]);
            *(float2*)&red[(wmg * 16 + gid + 8) * 66 + c] =
                make_float2(co[nd][2], co[nd][3]);
        }
    }
    __syncthreads();
    if (ws == 0) {
#pragma unroll
        for (int nd = 0; nd < 8; nd++) {
            int c = nd * 8 + 2 * tig;
            float2 r0 = *(float2*)&red[(wmg * 16 + gid) * 66 + c];
            float2 r1 = *(float2*)&red[(wmg * 16 + gid + 8) * 66 + c];
            int q = q0 + wm + gid;
            float2 o0 = make_float2(
                __uint_as_float(f2tf32(co[nd][0] + r0.x)),
                __uint_as_float(f2tf32(co[nd][1] + r0.y)));
            float2 o1 = make_float2(
                __uint_as_float(f2tf32(co[nd][2] + r1.x)),
                __uint_as_float(f2tf32(co[nd][3] + r1.y)));
            *(float2*)(O + (((size_t)((b * Ss + q) * NHh + h)) << 6) + c) = o0;
            *(float2*)(O + (((size_t)((b * Ss + q + 8) * NHh + h)) << 6) + c) = o1;
        }
    }
}

// ---------------------------------------------------------------------------
// Row LayerNorm over H=768
// ---------------------------------------------------------------------------
__global__ __launch_bounds__(256)
void ln_kernel(const float* __restrict__ X, const float* __restrict__ gamma,
               const float* __restrict__ beta, float* __restrict__ out)
{
    __shared__ float red[256];
    const int row = blockIdx.x;
    const int tid = threadIdx.x;
    const float* x = X + (size_t)row * Hh;

    float vals[3];
    float s = 0.f;
#pragma unroll
    for (int i = 0; i < 3; i++) {
        vals[i] = x[tid + i * 256];
        s += vals[i];
    }
    red[tid] = s;
    __syncthreads();
#pragma unroll
    for (int off = 128; off > 0; off >>= 1) {
        if (tid < off) red[tid] += red[tid + off];
        __syncthreads();
    }
    float mean = red[0] * (1.f / Hh);
    __syncthreads();

    float v = 0.f;
#pragma unroll
    for (int i = 0; i < 3; i++) {
        float d = vals[i] - mean;
        v += d * d;
    }
    red[tid] = v;
    __syncthreads();
#pragma unroll
    for (int off = 128; off > 0; off >>= 1) {
        if (tid < off) red[tid] += red[tid + off];
        __syncthreads();
    }
    float inv = rsqrtf(red[0] * (1.f / Hh) + 1e-5f);

#pragma unroll
    for (int i = 0; i < 3; i++) {
        int c = tid + i * 256;
        out[(size_t)row * Hh + c] = (vals[i] - mean) * inv * gamma[c] + beta[c];
    }
}

// avg_weights == 1/3 analytically (softmax over the adapter axis sums to 1)
__global__ void fill_kernel(float* __restrict__ p, int n4, float v)
{
    int i = blockIdx.x * blockDim.x + threadIdx.x;
    if (i < n4) {
        float4 f = make_float4(v, v, v, v);
        *(float4*)(p + (size_t)i * 4) = f;
    }
}

// ---------------------------------------------------------------------------
extern "C" void kernel_launch(void* const* d_in, const int* in_sizes, int n_in,
                              void* d_out, int out_size)
{
    const float* query = (const float*)d_in[0];
    const float* adap  = (const float*)d_in[1];
    const float* Wq = (const float*)d_in[2];  const float* bq = (const float*)d_in[3];
    const float* Wk = (const float*)d_in[4];  const float* bk = (const float*)d_in[5];
    const float* Wv = (const float*)d_in[6];  const float* bv = (const float*)d_in[7];
    const float* Wo = (const float*)d_in[8];  const float* bo = (const float*)d_in[9];
    const float* gamma = (const float*)d_in[10];
    const float* beta  = (const float*)d_in[11];
    float* out = (float*)d_out;

    float *Qp, *Kp, *Vp, *Att, *Oo, *Xq, *Xkv, *Wqc, *Wkc, *Wvc, *Woc;
    cudaGetSymbolAddress((void**)&Qp,  g_Q);
    cudaGetSymbolAddress((void**)&Kp,  g_K);
    cudaGetSymbolAddress((void**)&Vp,  g_V);
    cudaGetSymbolAddress((void**)&Att, g_att);
    cudaGetSymbolAddress((void**)&Oo,  g_O);
    cudaGetSymbolAddress((void**)&Xq,  g_Xq);
    cudaGetSymbolAddress((void**)&Xkv, g_Xkv);
    cudaGetSymbolAddress((void**)&Wqc, g_Wqc);
    cudaGetSymbolAddress((void**)&Wkc, g_Wkc);
    cudaGetSymbolAddress((void**)&Wvc, g_Wvc);
    cudaGetSymbolAddress((void**)&Woc, g_Woc);

    const int MQ = Bb * Ss;            // 4096
    const int MKV = Bb * Aa * Ss;      // 12288

    // Pre-round GEMM inputs to tf32 (producer-side rounding)
    {
        int nq = MQ * Hh / 4, nk = MKV * Hh / 4, nw = Hh * Hh / 4;
        cvt_tf32_kernel<<<(nq + 255) / 256, 256>>>(query, Xq,  nq);
        cvt_tf32_kernel<<<(nk + 255) / 256, 256>>>(adap,  Xkv, nk);
        cvt_tf32_kernel<<<(nw + 255) / 256, 256>>>(Wq, Wqc, nw);
        cvt_tf32_kernel<<<(nw + 255) / 256, 256>>>(Wk, Wkc, nw);
        cvt_tf32_kernel<<<(nw + 255) / 256, 256>>>(Wv, Wvc, nw);
        cvt_tf32_kernel<<<(nw + 255) / 256, 256>>>(Wo, Woc, nw);
    }

    cudaFuncSetAttribute(gemm_cp<false, true>,
                         cudaFuncAttributeMaxDynamicSharedMemorySize, GEMM_SMEM);
    cudaFuncSetAttribute(gemm_cp<true, false>,
                         cudaFuncAttributeMaxDynamicSharedMemorySize, GEMM_SMEM);

    dim3 blk(256);
    dim3 gq(Hh / 128, MQ / 128);       // (6, 32)
    dim3 gkv(Hh / 128, MKV / 128);     // (6, 96)

    // Projections (cp.async tf32 mma). Outputs tf32-rounded; Q pre-scaled 1/8.
    gemm_cp<false, true><<<gq,  blk, GEMM_SMEM>>>(Xq,  Wqc, bq, nullptr, Qp, MQ,  Hh, Hh, 0.125f);
    gemm_cp<false, true><<<gkv, blk, GEMM_SMEM>>>(Xkv, Wkc, bk, nullptr, Kp, MKV, Hh, Hh, 1.0f);
    gemm_cp<false, true><<<gkv, blk, GEMM_SMEM>>>(Xkv, Wvc, bv, nullptr, Vp, MKV, Hh, Hh, 1.0f);

    // Attention (3-stage cp.async, one sync per chunk)
    cudaFuncSetAttribute(attn6_kernel,
                         cudaFuncAttributeMaxDynamicSharedMemorySize, ATTN_SMEM);
    dim3 ga(Ss / 128, NHh, Bb);        // (8, 12, 4)
    attn6_kernel<<<ga, dim3(512), ATTN_SMEM>>>(Qp, Kp, Vp, Att);

    // Output projection + residual (attn output already tf32-rounded)
    gemm_cp<true, false><<<gq, blk, GEMM_SMEM>>>(Att, Woc, bo, query, Oo, MQ, Hh, Hh, 1.0f);

    // LayerNorm into first output region
    ln_kernel<<<MQ, blk>>>(Oo, gamma, beta, out);

    // avg_weights region = constant 1/3
    const int out0 = Bb * Ss * Hh;
    const int navg = out_size - out0;
    int n4 = navg / 4;
    fill_kernel<<<(n4 + 255) / 256, 256>>>(out + out0, n4, 1.0f / 3.0f);
}